// round 13
// baseline (speedup 1.0000x reference)
#include <cuda_runtime.h>
#include <cuda_fp16.h>
#include <cstdint>

// ---------------- problem constants (fixed by setup_inputs) ----------------
#define NN   50000
#define EE   800000
#define ET_MAX (EE+NN)
#define F0   128
#define NHEAD 4
#define C1   64
#define F1   (NHEAD*C1)   // 256
#define C2   16
#define F2   (NHEAD*C2)   // 64
#define NG   64
#define NOUT 32
#define NEG_SLOPE 0.2f

// ---------------- scratch (device globals; no allocation allowed) ----------
__device__ __half d_x16[NN*F0];
__device__ __half d_w1h[F0*F1];
__device__ __half d_w2h[F1*F2];
__device__ __half d_h1[NN*F1];
__device__ __half d_g1h[NN*F1];
__device__ __half d_h2[NN*F2];
__device__ float  d_g2[NN*F2];
__device__ float  d_as[NN*NHEAD];
__device__ float  d_ad[NN*NHEAD];
__device__ int    d_deg[NN];
__device__ int    d_rowptr[NN+1];
__device__ int    d_rowpos[NN];
__device__ int    d_csrsrc[ET_MAX];
__device__ float  d_pool[NG*F2];
__device__ float  d_cnt[NG];

// ---------------- helpers ---------------------------------------------------
__device__ __forceinline__ void cp_async16(void* smem, const void* gmem) {
    uint32_t s = (uint32_t)__cvta_generic_to_shared(smem);
    asm volatile("cp.async.ca.shared.global [%0], [%1], 16;" :: "r"(s), "l"(gmem));
}
__device__ __forceinline__ void cp_commit() { asm volatile("cp.async.commit_group;"); }
__device__ __forceinline__ void cp_wait0()  { asm volatile("cp.async.wait_group 0;"); }

__device__ __forceinline__ uint32_t smem_u32(const void* p) {
    return (uint32_t)__cvta_generic_to_shared(p);
}
__device__ __forceinline__ void ldsm_x4(uint32_t& r0, uint32_t& r1, uint32_t& r2, uint32_t& r3,
                                        uint32_t addr) {
    asm volatile("ldmatrix.sync.aligned.m8n8.x4.shared.b16 {%0,%1,%2,%3}, [%4];"
                 : "=r"(r0), "=r"(r1), "=r"(r2), "=r"(r3) : "r"(addr));
}
__device__ __forceinline__ void ldsm_x4_t(uint32_t& r0, uint32_t& r1, uint32_t& r2, uint32_t& r3,
                                          uint32_t addr) {
    asm volatile("ldmatrix.sync.aligned.m8n8.x4.trans.shared.b16 {%0,%1,%2,%3}, [%4];"
                 : "=r"(r0), "=r"(r1), "=r"(r2), "=r"(r3) : "r"(addr));
}
__device__ __forceinline__ void mma_f16(float* d, uint32_t a0, uint32_t a1, uint32_t a2,
                                        uint32_t a3, uint32_t b0, uint32_t b1) {
    asm volatile(
        "mma.sync.aligned.m16n8k16.row.col.f32.f16.f16.f32 "
        "{%0,%1,%2,%3}, {%4,%5,%6,%7}, {%8,%9}, {%0,%1,%2,%3};"
        : "+f"(d[0]), "+f"(d[1]), "+f"(d[2]), "+f"(d[3])
        : "r"(a0), "r"(a1), "r"(a2), "r"(a3), "r"(b0), "r"(b1));
}

// ---------------- fp32 -> fp16 convert (4 elems/thread) ---------------------
__global__ void f2h_kernel(const float4* __restrict__ in, uint2* __restrict__ out, int n4) {
    int i = blockIdx.x * blockDim.x + threadIdx.x;
    if (i >= n4) return;
    float4 v = in[i];
    __half2 a = __floats2half2_rn(v.x, v.y);
    __half2 b = __floats2half2_rn(v.z, v.w);
    uint2 o;
    o.x = *reinterpret_cast<uint32_t*>(&a);
    o.y = *reinterpret_cast<uint32_t*>(&b);
    out[i] = o;
}

// ---------------- fp16 HMMA GEMM (cp.async double-buffered, ldmatrix) ------
__global__ __launch_bounds__(256) void gemm_f16(
    const __half* __restrict__ A, const __half* __restrict__ B,
    __half* __restrict__ C, int M, int N, int K)
{
    __shared__ __half As[2][128][40];
    __shared__ __half Bs[2][32][72];

    int tid  = threadIdx.x;
    int warp = tid >> 5, lane = tid & 31;
    int wm = (warp & 3) * 32;
    int wn = (warp >> 2) * 32;
    int m0 = blockIdx.x * 128;
    int n0 = blockIdx.y * 64;

    int r  = lane >> 2;
    int cg = lane & 3;
    int g  = lane >> 3;
    int lr = lane & 7;
    int rowoff = (g & 1) * 8 + lr;
    int coloff = (g >> 1) * 8;

    int arow = tid >> 2;
    int akc  = (tid & 3) * 8;
    int brow = tid >> 3;
    int bnc  = (tid & 7) * 8;

    float acc[2][4][4];
#pragma unroll
    for (int i = 0; i < 2; i++)
#pragma unroll
        for (int j = 0; j < 4; j++)
#pragma unroll
            for (int q = 0; q < 4; q++) acc[i][j][q] = 0.f;

    int nk = K >> 5;

    {
        int gm0 = m0 + arow;       if (gm0 > M - 1) gm0 = M - 1;
        int gm1 = m0 + arow + 64;  if (gm1 > M - 1) gm1 = M - 1;
        cp_async16(&As[0][arow     ][akc], &A[(size_t)gm0 * K + akc]);
        cp_async16(&As[0][arow + 64][akc], &A[(size_t)gm1 * K + akc]);
        cp_async16(&Bs[0][brow][bnc], &B[(size_t)brow * N + n0 + bnc]);
        cp_commit();
    }

    for (int t = 0; t < nk; t++) {
        cp_wait0();
        __syncthreads();
        int buf = t & 1;

        if (t + 1 < nk) {
            int k0 = (t + 1) << 5;
            int gm0 = m0 + arow;       if (gm0 > M - 1) gm0 = M - 1;
            int gm1 = m0 + arow + 64;  if (gm1 > M - 1) gm1 = M - 1;
            cp_async16(&As[buf ^ 1][arow     ][akc], &A[(size_t)gm0 * K + k0 + akc]);
            cp_async16(&As[buf ^ 1][arow + 64][akc], &A[(size_t)gm1 * K + k0 + akc]);
            cp_async16(&Bs[buf ^ 1][brow][bnc], &B[(size_t)(k0 + brow) * N + n0 + bnc]);
            cp_commit();
        }

#pragma unroll
        for (int ks = 0; ks < 32; ks += 16) {
            uint32_t a[2][4];
#pragma unroll
            for (int mt = 0; mt < 2; mt++)
                ldsm_x4(a[mt][0], a[mt][1], a[mt][2], a[mt][3],
                        smem_u32(&As[buf][wm + mt * 16 + rowoff][ks + coloff]));
            uint32_t b[4][2];
#pragma unroll
            for (int np = 0; np < 2; np++) {
                uint32_t r0, r1, r2, r3;
                ldsm_x4_t(r0, r1, r2, r3,
                          smem_u32(&Bs[buf][ks + rowoff][wn + np * 16 + coloff]));
                b[np * 2][0] = r0; b[np * 2][1] = r1;
                b[np * 2 + 1][0] = r2; b[np * 2 + 1][1] = r3;
            }
#pragma unroll
            for (int mt = 0; mt < 2; mt++)
#pragma unroll
                for (int nt = 0; nt < 4; nt++)
                    mma_f16(acc[mt][nt], a[mt][0], a[mt][1], a[mt][2], a[mt][3],
                            b[nt][0], b[nt][1]);
        }
        __syncthreads();
    }

#pragma unroll
    for (int mt = 0; mt < 2; mt++) {
#pragma unroll
        for (int nt = 0; nt < 4; nt++) {
            int row = m0 + wm + mt * 16 + r;
            int col = n0 + wn + nt * 8 + 2 * cg;
            if (row < M) {
                __half2 o = __floats2half2_rn(acc[mt][nt][0], acc[mt][nt][1]);
                *reinterpret_cast<__half2*>(&C[(size_t)row * N + col]) = o;
            }
            if (row + 8 < M) {
                __half2 o = __floats2half2_rn(acc[mt][nt][2], acc[mt][nt][3]);
                *reinterpret_cast<__half2*>(&C[(size_t)(row + 8) * N + col]) = o;
            }
        }
    }
}

// ---------------- CSR build: histogram -> scan -> scatter -------------------
__global__ void hist_kernel(const int* __restrict__ ei, int* __restrict__ deg,
                            int E, int N) {
    int e = blockIdx.x * blockDim.x + threadIdx.x;
    if (e >= E + N) return;
    int d = (e < E) ? ei[E + e] : (e - E);
    atomicAdd(&deg[d], 1);
}

__global__ void scan_kernel(const int* __restrict__ deg, int* __restrict__ rowptr,
                            int* __restrict__ rowpos, int N) {
    __shared__ int sums[1024];
    int t = threadIdx.x;
    int CH = (N + 1023) / 1024;
    int b = t * CH, e = min(N, b + CH);
    int s = 0;
    for (int i = b; i < e; i++) s += deg[i];
    sums[t] = s;
    __syncthreads();
    for (int off = 1; off < 1024; off <<= 1) {
        int v = (t >= off) ? sums[t - off] : 0;
        __syncthreads();
        sums[t] += v;
        __syncthreads();
    }
    int run = (t == 0) ? 0 : sums[t - 1];
    for (int i = b; i < e; i++) {
        rowptr[i] = run;
        rowpos[i] = run;
        run += deg[i];
    }
    if (t == 1023) rowptr[N] = sums[1023];
}

__global__ void scatter_kernel(const int* __restrict__ ei, int* __restrict__ rowpos,
                               int* __restrict__ csrsrc, int E, int N) {
    int e = blockIdx.x * blockDim.x + threadIdx.x;
    if (e >= E + N) return;
    int s, d;
    if (e < E) { s = ei[e]; d = ei[E + e]; } else { s = d = e - E; }
    int pos = atomicAdd(&rowpos[d], 1);
    csrsrc[pos] = s;
}

// ---------------- per-node attention logits (fp16 features) ----------------
template<int C>
__global__ void alpha_kernel(const __half* __restrict__ h,
                             const float* __restrict__ asr, const float* __restrict__ adt,
                             float* __restrict__ outs, float* __restrict__ outd, int N) {
    int idx = blockIdx.x * blockDim.x + threadIdx.x;
    if (idx >= N * NHEAD) return;
    int hh = idx & (NHEAD - 1);
    const __half* hp = h + (size_t)idx * C;
    const float* ap = asr + hh * C;
    const float* dp = adt + hh * C;
    float ss = 0.f, dd = 0.f;
#pragma unroll
    for (int i = 0; i < C; i += 8) {
        uint4 raw = *reinterpret_cast<const uint4*>(hp + i);
        float2 f0 = __half22float2(*reinterpret_cast<__half2*>(&raw.x));
        float2 f1 = __half22float2(*reinterpret_cast<__half2*>(&raw.y));
        float2 f2 = __half22float2(*reinterpret_cast<__half2*>(&raw.z));
        float2 f3 = __half22float2(*reinterpret_cast<__half2*>(&raw.w));
        float4 a0 = *reinterpret_cast<const float4*>(ap + i);
        float4 a1 = *reinterpret_cast<const float4*>(ap + i + 4);
        float4 d0 = *reinterpret_cast<const float4*>(dp + i);
        float4 d1 = *reinterpret_cast<const float4*>(dp + i + 4);
        ss += f0.x * a0.x + f0.y * a0.y + f1.x * a0.z + f1.y * a0.w
            + f2.x * a1.x + f2.y * a1.y + f3.x * a1.z + f3.y * a1.w;
        dd += f0.x * d0.x + f0.y * d0.y + f1.x * d0.z + f1.y * d0.w
            + f2.x * d1.x + f2.y * d1.y + f3.x * d1.z + f3.y * d1.w;
    }
    outs[idx] = ss;
    outd[idx] = dd;
}

// ---------------- pull aggregation layer 1: TWO warps per dst --------------
// Warp owns 128 of 256 channels; lane owns 4 (8B/edge, 256B coalesced/warp).
// Both warps redundantly compute wsum. 2x edge unroll.
__global__ void agg1_kernel(const int* __restrict__ rowptr, const int* __restrict__ csrsrc,
                            const float* __restrict__ as, const float* __restrict__ ad,
                            const __half* __restrict__ h,
                            const float* __restrict__ bias, __half* __restrict__ out, int N) {
    int gwid = (blockIdx.x * blockDim.x + threadIdx.x) >> 5;
    int lane = threadIdx.x & 31;
    if (gwid >= N * 2) return;
    int n = gwid >> 1;
    int half = gwid & 1;
    int c0 = half * 128 + lane * 4;     // 4 channels per lane
    int hh = c0 >> 6;                   // head
    int beg = rowptr[n], end = rowptr[n + 1];
    float adh = ad[(size_t)n * 4 + hh];
    float4 acc = make_float4(0.f, 0.f, 0.f, 0.f);
    float wsum = 0.f;
    int i = beg;
    for (; i + 1 < end; i += 2) {
        int s0 = csrsrc[i], s1 = csrsrc[i + 1];
        float as0 = as[(size_t)s0 * 4 + hh];
        float as1 = as[(size_t)s1 * 4 + hh];
        uint2 ra = *reinterpret_cast<const uint2*>(h + (size_t)s0 * F1 + c0);
        uint2 rb = *reinterpret_cast<const uint2*>(h + (size_t)s1 * F1 + c0);
        float t0 = as0 + adh; t0 = t0 > 0.f ? t0 : NEG_SLOPE * t0;
        float t1 = as1 + adh; t1 = t1 > 0.f ? t1 : NEG_SLOPE * t1;
        float w0 = __expf(t0), w1 = __expf(t1);
        wsum += w0 + w1;
        float2 f;
        f = __half22float2(*reinterpret_cast<__half2*>(&ra.x)); acc.x += w0 * f.x; acc.y += w0 * f.y;
        f = __half22float2(*reinterpret_cast<__half2*>(&ra.y)); acc.z += w0 * f.x; acc.w += w0 * f.y;
        f = __half22float2(*reinterpret_cast<__half2*>(&rb.x)); acc.x += w1 * f.x; acc.y += w1 * f.y;
        f = __half22float2(*reinterpret_cast<__half2*>(&rb.y)); acc.z += w1 * f.x; acc.w += w1 * f.y;
    }
    if (i < end) {
        int s0 = csrsrc[i];
        float as0 = as[(size_t)s0 * 4 + hh];
        float t0 = as0 + adh; t0 = t0 > 0.f ? t0 : NEG_SLOPE * t0;
        float w0 = __expf(t0);
        wsum += w0;
        uint2 ra = *reinterpret_cast<const uint2*>(h + (size_t)s0 * F1 + c0);
        float2 f;
        f = __half22float2(*reinterpret_cast<__half2*>(&ra.x)); acc.x += w0 * f.x; acc.y += w0 * f.y;
        f = __half22float2(*reinterpret_cast<__half2*>(&ra.y)); acc.z += w0 * f.x; acc.w += w0 * f.y;
    }
    float inv = 1.f / wsum;
    float4 b = *reinterpret_cast<const float4*>(bias + c0);
    __half2 p0 = __floats2half2_rn(fmaxf(acc.x * inv + b.x, 0.f), fmaxf(acc.y * inv + b.y, 0.f));
    __half2 p1 = __floats2half2_rn(fmaxf(acc.z * inv + b.z, 0.f), fmaxf(acc.w * inv + b.w, 0.f));
    uint2 o;
    o.x = *reinterpret_cast<uint32_t*>(&p0);
    o.y = *reinterpret_cast<uint32_t*>(&p1);
    *reinterpret_cast<uint2*>(out + (size_t)n * F1 + c0) = o;
}

// ---------------- pull aggregation layer 2 (warp per dst node) -------------
__global__ void agg2_kernel(const int* __restrict__ rowptr, const int* __restrict__ csrsrc,
                            const float* __restrict__ as, const float* __restrict__ ad,
                            const __half* __restrict__ h,
                            const float* __restrict__ bias, float* __restrict__ out, int N) {
    int gw = (blockIdx.x * blockDim.x + threadIdx.x) >> 5;
    int lane = threadIdx.x & 31;
    if (gw >= N) return;
    int hh = lane >> 3;
    int beg = rowptr[gw], end = rowptr[gw + 1];
    float adh = ad[(size_t)gw * 4 + hh];
    float acc0 = 0.f, acc1 = 0.f, wsum = 0.f;
    int i = beg;
    for (; i + 1 < end; i += 2) {
        int s0 = csrsrc[i], s1 = csrsrc[i + 1];
        float as0 = as[(size_t)s0 * 4 + hh];
        float as1 = as[(size_t)s1 * 4 + hh];
        __half2 hv0 = *reinterpret_cast<const __half2*>(h + (size_t)s0 * F2 + lane * 2);
        __half2 hv1 = *reinterpret_cast<const __half2*>(h + (size_t)s1 * F2 + lane * 2);
        float t0 = as0 + adh; t0 = t0 > 0.f ? t0 : NEG_SLOPE * t0;
        float t1 = as1 + adh; t1 = t1 > 0.f ? t1 : NEG_SLOPE * t1;
        float w0 = __expf(t0), w1 = __expf(t1);
        wsum += w0 + w1;
        float2 v0 = __half22float2(hv0), v1 = __half22float2(hv1);
        acc0 += w0 * v0.x + w1 * v1.x;
        acc1 += w0 * v0.y + w1 * v1.y;
    }
    if (i < end) {
        int s0 = csrsrc[i];
        float as0 = as[(size_t)s0 * 4 + hh];
        float t0 = as0 + adh; t0 = t0 > 0.f ? t0 : NEG_SLOPE * t0;
        float w0 = __expf(t0);
        wsum += w0;
        float2 v0 = __half22float2(*reinterpret_cast<const __half2*>(h + (size_t)s0 * F2 + lane * 2));
        acc0 += w0 * v0.x;
        acc1 += w0 * v0.y;
    }
    float inv = 1.f / wsum;
    int c = lane * 2;
    float o0 = acc0 * inv + bias[c];
    float o1 = acc1 * inv + bias[c + 1];
    float2 o = make_float2(o0 > 0.f ? o0 : 0.f, o1 > 0.f ? o1 : 0.f);
    *reinterpret_cast<float2*>(out + (size_t)gw * F2 + c) = o;
}

// ---------------- pooling (batch sorted; 8 nodes/thread run-length) --------
#define POOL_CH 8
__global__ void pool_kernel(const float* __restrict__ g, const int* __restrict__ batch,
                            float* __restrict__ pool, int N) {
    int c = blockIdx.y;
    int t = blockIdx.x * blockDim.x + threadIdx.x;
    int n0 = t * POOL_CH;
    if (n0 >= N) return;
    int n1 = min(N, n0 + POOL_CH);
    int cur = batch[n0];
    float acc = 0.f;
    for (int n = n0; n < n1; n++) {
        int bb = batch[n];
        if (bb != cur) { atomicAdd(&pool[cur * F2 + c], acc); cur = bb; acc = 0.f; }
        acc += g[(size_t)n * F2 + c];
    }
    atomicAdd(&pool[cur * F2 + c], acc);
}

__global__ void count_kernel(const int* __restrict__ batch, float* __restrict__ cnt, int N) {
    int t = blockIdx.x * blockDim.x + threadIdx.x;
    int n0 = t * POOL_CH;
    if (n0 >= N) return;
    int n1 = min(N, n0 + POOL_CH);
    int cur = batch[n0];
    float acc = 0.f;
    for (int n = n0; n < n1; n++) {
        int bb = batch[n];
        if (bb != cur) { atomicAdd(&cnt[cur], acc); cur = bb; acc = 0.f; }
        acc += 1.f;
    }
    atomicAdd(&cnt[cur], acc);
}

// ---------------- final FC --------------------------------------------------
__global__ void fc_kernel(const float* __restrict__ pool, const float* __restrict__ cnt,
                          const float* __restrict__ w, const float* __restrict__ b,
                          float* __restrict__ out) {
    int g = blockIdx.x;
    int j = threadIdx.x;
    float inv = 1.f / fmaxf(cnt[g], 1.f);
    float acc = b[j];
#pragma unroll
    for (int c = 0; c < F2; c++)
        acc += pool[g * F2 + c] * inv * w[c * NOUT + j];
    out[g * NOUT + j] = acc;
}

// ---------------- launch ----------------------------------------------------
extern "C" void kernel_launch(void* const* d_in, const int* in_sizes, int n_in,
                              void* d_out, int out_size) {
    const float* x      = (const float*)d_in[0];
    const int*   ei     = (const int*)  d_in[1];
    const int*   batch  = (const int*)  d_in[2];
    const float* W1     = (const float*)d_in[3];
    const float* a_src1 = (const float*)d_in[4];
    const float* a_dst1 = (const float*)d_in[5];
    const float* b1     = (const float*)d_in[6];
    const float* W2     = (const float*)d_in[7];
    const float* a_src2 = (const float*)d_in[8];
    const float* a_dst2 = (const float*)d_in[9];
    const float* b2     = (const float*)d_in[10];
    const float* fcw    = (const float*)d_in[11];
    const float* fcb    = (const float*)d_in[12];

    int N = in_sizes[0] / F0;     // 50000
    int E = in_sizes[1] / 2;      // 800000
    int ET = E + N;

    __half *p_x16, *p_w1h, *p_w2h, *p_h1, *p_g1h, *p_h2;
    float *p_g2, *p_as, *p_ad, *p_pool, *p_cnt;
    int *p_deg, *p_rowptr, *p_rowpos, *p_csrsrc;
    cudaGetSymbolAddress((void**)&p_x16, d_x16);
    cudaGetSymbolAddress((void**)&p_w1h, d_w1h);
    cudaGetSymbolAddress((void**)&p_w2h, d_w2h);
    cudaGetSymbolAddress((void**)&p_h1, d_h1);
    cudaGetSymbolAddress((void**)&p_g1h, d_g1h);
    cudaGetSymbolAddress((void**)&p_h2, d_h2);
    cudaGetSymbolAddress((void**)&p_g2, d_g2);
    cudaGetSymbolAddress((void**)&p_as, d_as);
    cudaGetSymbolAddress((void**)&p_ad, d_ad);
    cudaGetSymbolAddress((void**)&p_deg, d_deg);
    cudaGetSymbolAddress((void**)&p_rowptr, d_rowptr);
    cudaGetSymbolAddress((void**)&p_rowpos, d_rowpos);
    cudaGetSymbolAddress((void**)&p_csrsrc, d_csrsrc);
    cudaGetSymbolAddress((void**)&p_pool, d_pool);
    cudaGetSymbolAddress((void**)&p_cnt, d_cnt);

    float* out = (float*)d_out;

    static cudaStream_t s2 = nullptr;
    static cudaEvent_t ev_fork = nullptr, ev_join = nullptr;
    if (s2 == nullptr) {
        cudaStreamCreateWithFlags(&s2, cudaStreamNonBlocking);
        cudaEventCreateWithFlags(&ev_fork, cudaEventDisableTiming);
        cudaEventCreateWithFlags(&ev_join, cudaEventDisableTiming);
    }

    // ---- fork: CSR build + pooling init on s2 (depends only on ei/batch) ----
    cudaEventRecord(ev_fork, 0);
    cudaStreamWaitEvent(s2, ev_fork, 0);
    cudaMemsetAsync(p_deg, 0, (size_t)N * sizeof(int), s2);
    hist_kernel<<<(ET + 255) / 256, 256, 0, s2>>>(ei, p_deg, E, N);
    scan_kernel<<<1, 1024, 0, s2>>>(p_deg, p_rowptr, p_rowpos, N);
    scatter_kernel<<<(ET + 255) / 256, 256, 0, s2>>>(ei, p_rowpos, p_csrsrc, E, N);
    cudaMemsetAsync(p_pool, 0, (size_t)NG * F2 * sizeof(float), s2);
    cudaMemsetAsync(p_cnt, 0, (size_t)NG * sizeof(float), s2);
    count_kernel<<<(((N + POOL_CH - 1) / POOL_CH) + 127) / 128, 128, 0, s2>>>(batch, p_cnt, N);
    cudaEventRecord(ev_join, s2);

    // ---- main stream: fp16 conversion + GEMM1 + alpha1 (independent) ----
    f2h_kernel<<<((N * F0 / 4) + 255) / 256, 256>>>((const float4*)x, (uint2*)p_x16, N * F0 / 4);
    f2h_kernel<<<((F0 * F1 / 4) + 255) / 256, 256>>>((const float4*)W1, (uint2*)p_w1h, F0 * F1 / 4);
    f2h_kernel<<<((F1 * F2 / 4) + 255) / 256, 256>>>((const float4*)W2, (uint2*)p_w2h, F1 * F2 / 4);
    {
        dim3 grid((N + 127) / 128, F1 / 64);
        gemm_f16<<<grid, 256>>>(p_x16, p_w1h, p_h1, N, F1, F0);
    }
    alpha_kernel<C1><<<(N * NHEAD + 255) / 256, 256>>>(p_h1, a_src1, a_dst1, p_as, p_ad, N);

    // ---- join: aggregation needs the CSR ----
    cudaStreamWaitEvent(0, ev_join, 0);
    agg1_kernel<<<(N * 2 * 32 + 255) / 256, 256>>>(p_rowptr, p_csrsrc, p_as, p_ad,
                                                   p_h1, b1, p_g1h, N);

    // ---------------- layer 2 ----------------
    {
        dim3 grid((N + 127) / 128, F2 / 64);
        gemm_f16<<<grid, 256>>>(p_g1h, p_w2h, p_h2, N, F2, F1);
    }
    alpha_kernel<C2><<<(N * NHEAD + 255) / 256, 256>>>(p_h2, a_src2, a_dst2, p_as, p_ad, N);
    agg2_kernel<<<(N * 32 + 255) / 256, 256>>>(p_rowptr, p_csrsrc, p_as, p_ad,
                                               p_h2, b2, p_g2, N);

    // ---------------- pooling + FC ----------------
    {
        int nthreads = (N + POOL_CH - 1) / POOL_CH;
        dim3 grid((nthreads + 127) / 128, F2);
        pool_kernel<<<grid, 128>>>(p_g2, batch, p_pool, N);
    }
    fc_kernel<<<NG, NOUT>>>(p_pool, p_cnt, fcw, fcb, out);
}

// round 15
// speedup vs baseline: 1.0936x; 1.0936x over previous
#include <cuda_runtime.h>
#include <cuda_fp16.h>
#include <cstdint>

// ---------------- problem constants (fixed by setup_inputs) ----------------
#define NN   50000
#define EE   800000
#define ET_MAX (EE+NN)
#define F0   128
#define NHEAD 4
#define C1   64
#define F1   (NHEAD*C1)   // 256
#define C2   16
#define F2   (NHEAD*C2)   // 64
#define NG   64
#define NOUT 32
#define NEG_SLOPE 0.2f

// ---------------- scratch (device globals; no allocation allowed) ----------
__device__ __half d_x16[NN*F0];
__device__ __half d_w1h[F0*F1];
__device__ __half d_w2h[F1*F2];
__device__ __half d_h1[NN*F1];
__device__ __half d_g1h[NN*F1];
__device__ __half d_h2[NN*F2];
__device__ float  d_g2[NN*F2];
__device__ float  d_as[NN*NHEAD];
__device__ float  d_ad[NN*NHEAD];
__device__ int    d_deg[NN];
__device__ int    d_rowptr[NN+1];
__device__ int    d_rowpos[NN];
__device__ int    d_csrsrc[ET_MAX];
__device__ float  d_pool[NG*F2];
__device__ float  d_cnt[NG];

// ---------------- helpers ---------------------------------------------------
__device__ __forceinline__ void cp_async16(void* smem, const void* gmem) {
    uint32_t s = (uint32_t)__cvta_generic_to_shared(smem);
    asm volatile("cp.async.ca.shared.global [%0], [%1], 16;" :: "r"(s), "l"(gmem));
}
__device__ __forceinline__ void cp_commit() { asm volatile("cp.async.commit_group;"); }
__device__ __forceinline__ void cp_wait0()  { asm volatile("cp.async.wait_group 0;"); }

__device__ __forceinline__ uint32_t smem_u32(const void* p) {
    return (uint32_t)__cvta_generic_to_shared(p);
}
__device__ __forceinline__ void ldsm_x4(uint32_t& r0, uint32_t& r1, uint32_t& r2, uint32_t& r3,
                                        uint32_t addr) {
    asm volatile("ldmatrix.sync.aligned.m8n8.x4.shared.b16 {%0,%1,%2,%3}, [%4];"
                 : "=r"(r0), "=r"(r1), "=r"(r2), "=r"(r3) : "r"(addr));
}
__device__ __forceinline__ void ldsm_x4_t(uint32_t& r0, uint32_t& r1, uint32_t& r2, uint32_t& r3,
                                          uint32_t addr) {
    asm volatile("ldmatrix.sync.aligned.m8n8.x4.trans.shared.b16 {%0,%1,%2,%3}, [%4];"
                 : "=r"(r0), "=r"(r1), "=r"(r2), "=r"(r3) : "r"(addr));
}
__device__ __forceinline__ void mma_f16(float* d, uint32_t a0, uint32_t a1, uint32_t a2,
                                        uint32_t a3, uint32_t b0, uint32_t b1) {
    asm volatile(
        "mma.sync.aligned.m16n8k16.row.col.f32.f16.f16.f32 "
        "{%0,%1,%2,%3}, {%4,%5,%6,%7}, {%8,%9}, {%0,%1,%2,%3};"
        : "+f"(d[0]), "+f"(d[1]), "+f"(d[2]), "+f"(d[3])
        : "r"(a0), "r"(a1), "r"(a2), "r"(a3), "r"(b0), "r"(b1));
}

// ---------------- fp32 -> fp16 convert (4 elems/thread) ---------------------
__global__ void f2h_kernel(const float4* __restrict__ in, uint2* __restrict__ out, int n4) {
    int i = blockIdx.x * blockDim.x + threadIdx.x;
    if (i >= n4) return;
    float4 v = in[i];
    __half2 a = __floats2half2_rn(v.x, v.y);
    __half2 b = __floats2half2_rn(v.z, v.w);
    uint2 o;
    o.x = *reinterpret_cast<uint32_t*>(&a);
    o.y = *reinterpret_cast<uint32_t*>(&b);
    out[i] = o;
}

// ---------------- fp16 HMMA GEMM (cp.async double-buffered, ldmatrix) ------
__global__ __launch_bounds__(256) void gemm_f16(
    const __half* __restrict__ A, const __half* __restrict__ B,
    __half* __restrict__ C, int M, int N, int K)
{
    __shared__ __half As[2][128][40];
    __shared__ __half Bs[2][32][72];

    int tid  = threadIdx.x;
    int warp = tid >> 5, lane = tid & 31;
    int wm = (warp & 3) * 32;
    int wn = (warp >> 2) * 32;
    int m0 = blockIdx.x * 128;
    int n0 = blockIdx.y * 64;

    int r  = lane >> 2;
    int cg = lane & 3;
    int g  = lane >> 3;
    int lr = lane & 7;
    int rowoff = (g & 1) * 8 + lr;
    int coloff = (g >> 1) * 8;

    int arow = tid >> 2;
    int akc  = (tid & 3) * 8;
    int brow = tid >> 3;
    int bnc  = (tid & 7) * 8;

    float acc[2][4][4];
#pragma unroll
    for (int i = 0; i < 2; i++)
#pragma unroll
        for (int j = 0; j < 4; j++)
#pragma unroll
            for (int q = 0; q < 4; q++) acc[i][j][q] = 0.f;

    int nk = K >> 5;

    {
        int gm0 = m0 + arow;       if (gm0 > M - 1) gm0 = M - 1;
        int gm1 = m0 + arow + 64;  if (gm1 > M - 1) gm1 = M - 1;
        cp_async16(&As[0][arow     ][akc], &A[(size_t)gm0 * K + akc]);
        cp_async16(&As[0][arow + 64][akc], &A[(size_t)gm1 * K + akc]);
        cp_async16(&Bs[0][brow][bnc], &B[(size_t)brow * N + n0 + bnc]);
        cp_commit();
    }

    for (int t = 0; t < nk; t++) {
        cp_wait0();
        __syncthreads();
        int buf = t & 1;

        if (t + 1 < nk) {
            int k0 = (t + 1) << 5;
            int gm0 = m0 + arow;       if (gm0 > M - 1) gm0 = M - 1;
            int gm1 = m0 + arow + 64;  if (gm1 > M - 1) gm1 = M - 1;
            cp_async16(&As[buf ^ 1][arow     ][akc], &A[(size_t)gm0 * K + k0 + akc]);
            cp_async16(&As[buf ^ 1][arow + 64][akc], &A[(size_t)gm1 * K + k0 + akc]);
            cp_async16(&Bs[buf ^ 1][brow][bnc], &B[(size_t)(k0 + brow) * N + n0 + bnc]);
            cp_commit();
        }

#pragma unroll
        for (int ks = 0; ks < 32; ks += 16) {
            uint32_t a[2][4];
#pragma unroll
            for (int mt = 0; mt < 2; mt++)
                ldsm_x4(a[mt][0], a[mt][1], a[mt][2], a[mt][3],
                        smem_u32(&As[buf][wm + mt * 16 + rowoff][ks + coloff]));
            uint32_t b[4][2];
#pragma unroll
            for (int np = 0; np < 2; np++) {
                uint32_t r0, r1, r2, r3;
                ldsm_x4_t(r0, r1, r2, r3,
                          smem_u32(&Bs[buf][ks + rowoff][wn + np * 16 + coloff]));
                b[np * 2][0] = r0; b[np * 2][1] = r1;
                b[np * 2 + 1][0] = r2; b[np * 2 + 1][1] = r3;
            }
#pragma unroll
            for (int mt = 0; mt < 2; mt++)
#pragma unroll
                for (int nt = 0; nt < 4; nt++)
                    mma_f16(acc[mt][nt], a[mt][0], a[mt][1], a[mt][2], a[mt][3],
                            b[nt][0], b[nt][1]);
        }
        __syncthreads();
    }

#pragma unroll
    for (int mt = 0; mt < 2; mt++) {
#pragma unroll
        for (int nt = 0; nt < 4; nt++) {
            int row = m0 + wm + mt * 16 + r;
            int col = n0 + wn + nt * 8 + 2 * cg;
            if (row < M) {
                __half2 o = __floats2half2_rn(acc[mt][nt][0], acc[mt][nt][1]);
                *reinterpret_cast<__half2*>(&C[(size_t)row * N + col]) = o;
            }
            if (row + 8 < M) {
                __half2 o = __floats2half2_rn(acc[mt][nt][2], acc[mt][nt][3]);
                *reinterpret_cast<__half2*>(&C[(size_t)(row + 8) * N + col]) = o;
            }
        }
    }
}

// ---------------- CSR build: histogram -> scan -> scatter -------------------
__global__ void hist_kernel(const int* __restrict__ ei, int* __restrict__ deg,
                            int E, int N) {
    int e = blockIdx.x * blockDim.x + threadIdx.x;
    if (e >= E + N) return;
    int d = (e < E) ? ei[E + e] : (e - E);
    atomicAdd(&deg[d], 1);
}

__global__ void scan_kernel(const int* __restrict__ deg, int* __restrict__ rowptr,
                            int* __restrict__ rowpos, int N) {
    __shared__ int sums[1024];
    int t = threadIdx.x;
    int CH = (N + 1023) / 1024;
    int b = t * CH, e = min(N, b + CH);
    int s = 0;
    for (int i = b; i < e; i++) s += deg[i];
    sums[t] = s;
    __syncthreads();
    for (int off = 1; off < 1024; off <<= 1) {
        int v = (t >= off) ? sums[t - off] : 0;
        __syncthreads();
        sums[t] += v;
        __syncthreads();
    }
    int run = (t == 0) ? 0 : sums[t - 1];
    for (int i = b; i < e; i++) {
        rowptr[i] = run;
        rowpos[i] = run;
        run += deg[i];
    }
    if (t == 1023) rowptr[N] = sums[1023];
}

__global__ void scatter_kernel(const int* __restrict__ ei, int* __restrict__ rowpos,
                               int* __restrict__ csrsrc, int E, int N) {
    int e = blockIdx.x * blockDim.x + threadIdx.x;
    if (e >= E + N) return;
    int s, d;
    if (e < E) { s = ei[e]; d = ei[E + e]; } else { s = d = e - E; }
    int pos = atomicAdd(&rowpos[d], 1);
    csrsrc[pos] = s;
}

// ---------------- per-node attention logits (fp16 features) ----------------
template<int C>
__global__ void alpha_kernel(const __half* __restrict__ h,
                             const float* __restrict__ asr, const float* __restrict__ adt,
                             float* __restrict__ outs, float* __restrict__ outd, int N) {
    int idx = blockIdx.x * blockDim.x + threadIdx.x;
    if (idx >= N * NHEAD) return;
    int hh = idx & (NHEAD - 1);
    const __half* hp = h + (size_t)idx * C;
    const float* ap = asr + hh * C;
    const float* dp = adt + hh * C;
    float ss = 0.f, dd = 0.f;
#pragma unroll
    for (int i = 0; i < C; i += 8) {
        uint4 raw = *reinterpret_cast<const uint4*>(hp + i);
        float2 f0 = __half22float2(*reinterpret_cast<__half2*>(&raw.x));
        float2 f1 = __half22float2(*reinterpret_cast<__half2*>(&raw.y));
        float2 f2 = __half22float2(*reinterpret_cast<__half2*>(&raw.z));
        float2 f3 = __half22float2(*reinterpret_cast<__half2*>(&raw.w));
        float4 a0 = *reinterpret_cast<const float4*>(ap + i);
        float4 a1 = *reinterpret_cast<const float4*>(ap + i + 4);
        float4 d0 = *reinterpret_cast<const float4*>(dp + i);
        float4 d1 = *reinterpret_cast<const float4*>(dp + i + 4);
        ss += f0.x * a0.x + f0.y * a0.y + f1.x * a0.z + f1.y * a0.w
            + f2.x * a1.x + f2.y * a1.y + f3.x * a1.z + f3.y * a1.w;
        dd += f0.x * d0.x + f0.y * d0.y + f1.x * d0.z + f1.y * d0.w
            + f2.x * d1.x + f2.y * d1.y + f3.x * d1.z + f3.y * d1.w;
    }
    outs[idx] = ss;
    outd[idx] = dd;
}

// ---------------- pull aggregation layer 1 (warp per dst, all heads) -------
// Round-12 winner: lane owns 8 contiguous channels (16B gather), 2x unroll.
__global__ void agg1_kernel(const int* __restrict__ rowptr, const int* __restrict__ csrsrc,
                            const float* __restrict__ as, const float* __restrict__ ad,
                            const __half* __restrict__ h,
                            const float* __restrict__ bias, __half* __restrict__ out, int N) {
    int gw = (blockIdx.x * blockDim.x + threadIdx.x) >> 5;
    int lane = threadIdx.x & 31;
    if (gw >= N) return;
    int hh = lane >> 3;
    int beg = rowptr[gw], end = rowptr[gw + 1];
    float adh = ad[(size_t)gw * 4 + hh];
    float4 acc0 = make_float4(0.f, 0.f, 0.f, 0.f);
    float4 acc1 = make_float4(0.f, 0.f, 0.f, 0.f);
    float wsum = 0.f;
    int i = beg;
    for (; i + 1 < end; i += 2) {
        int s0 = csrsrc[i], s1 = csrsrc[i + 1];
        float as0 = as[(size_t)s0 * 4 + hh];
        float as1 = as[(size_t)s1 * 4 + hh];
        uint4 ra = *reinterpret_cast<const uint4*>(h + (size_t)s0 * F1 + lane * 8);
        uint4 rb = *reinterpret_cast<const uint4*>(h + (size_t)s1 * F1 + lane * 8);
        float t0 = as0 + adh; t0 = t0 > 0.f ? t0 : NEG_SLOPE * t0;
        float t1 = as1 + adh; t1 = t1 > 0.f ? t1 : NEG_SLOPE * t1;
        float w0 = __expf(t0), w1 = __expf(t1);
        wsum += w0 + w1;
        float2 f;
        f = __half22float2(*reinterpret_cast<__half2*>(&ra.x)); acc0.x += w0 * f.x; acc0.y += w0 * f.y;
        f = __half22float2(*reinterpret_cast<__half2*>(&ra.y)); acc0.z += w0 * f.x; acc0.w += w0 * f.y;
        f = __half22float2(*reinterpret_cast<__half2*>(&ra.z)); acc1.x += w0 * f.x; acc1.y += w0 * f.y;
        f = __half22float2(*reinterpret_cast<__half2*>(&ra.w)); acc1.z += w0 * f.x; acc1.w += w0 * f.y;
        f = __half22float2(*reinterpret_cast<__half2*>(&rb.x)); acc0.x += w1 * f.x; acc0.y += w1 * f.y;
        f = __half22float2(*reinterpret_cast<__half2*>(&rb.y)); acc0.z += w1 * f.x; acc0.w += w1 * f.y;
        f = __half22float2(*reinterpret_cast<__half2*>(&rb.z)); acc1.x += w1 * f.x; acc1.y += w1 * f.y;
        f = __half22float2(*reinterpret_cast<__half2*>(&rb.w)); acc1.z += w1 * f.x; acc1.w += w1 * f.y;
    }
    if (i < end) {
        int s0 = csrsrc[i];
        float as0 = as[(size_t)s0 * 4 + hh];
        float t0 = as0 + adh; t0 = t0 > 0.f ? t0 : NEG_SLOPE * t0;
        float w0 = __expf(t0);
        wsum += w0;
        uint4 ra = *reinterpret_cast<const uint4*>(h + (size_t)s0 * F1 + lane * 8);
        float2 f;
        f = __half22float2(*reinterpret_cast<__half2*>(&ra.x)); acc0.x += w0 * f.x; acc0.y += w0 * f.y;
        f = __half22float2(*reinterpret_cast<__half2*>(&ra.y)); acc0.z += w0 * f.x; acc0.w += w0 * f.y;
        f = __half22float2(*reinterpret_cast<__half2*>(&ra.z)); acc1.x += w0 * f.x; acc1.y += w0 * f.y;
        f = __half22float2(*reinterpret_cast<__half2*>(&ra.w)); acc1.z += w0 * f.x; acc1.w += w0 * f.y;
    }
    float inv = 1.f / wsum;
    int c = lane * 8;
    const float4* bp = reinterpret_cast<const float4*>(bias + c);
    float4 b0 = bp[0], b1 = bp[1];
    __half2 p0 = __floats2half2_rn(fmaxf(acc0.x * inv + b0.x, 0.f), fmaxf(acc0.y * inv + b0.y, 0.f));
    __half2 p1 = __floats2half2_rn(fmaxf(acc0.z * inv + b0.z, 0.f), fmaxf(acc0.w * inv + b0.w, 0.f));
    __half2 p2 = __floats2half2_rn(fmaxf(acc1.x * inv + b1.x, 0.f), fmaxf(acc1.y * inv + b1.y, 0.f));
    __half2 p3 = __floats2half2_rn(fmaxf(acc1.z * inv + b1.z, 0.f), fmaxf(acc1.w * inv + b1.w, 0.f));
    uint4 o;
    o.x = *reinterpret_cast<uint32_t*>(&p0);
    o.y = *reinterpret_cast<uint32_t*>(&p1);
    o.z = *reinterpret_cast<uint32_t*>(&p2);
    o.w = *reinterpret_cast<uint32_t*>(&p3);
    *reinterpret_cast<uint4*>(out + (size_t)gw * F1 + c) = o;
}

// ---------------- pull aggregation layer 2: half-warp per edge -------------
// Lanes 0-15 take even edges, 16-31 odd edges; lane owns 4 channels (8B).
// Distinct edges per half -> no duplicated index/exp work; combine via shfl.
__global__ void agg2_kernel(const int* __restrict__ rowptr, const int* __restrict__ csrsrc,
                            const float* __restrict__ as, const float* __restrict__ ad,
                            const __half* __restrict__ h,
                            const float* __restrict__ bias, float* __restrict__ out, int N) {
    int gw = (blockIdx.x * blockDim.x + threadIdx.x) >> 5;
    int lane = threadIdx.x & 31;
    if (gw >= N) return;
    int hl = lane >> 4;          // half index: 0 even edges, 1 odd edges
    int cl = lane & 15;          // channel group
    int c0 = cl * 4;             // 4 halves per lane
    int hh = c0 >> 4;            // head = c0/C2
    int beg = rowptr[gw], end = rowptr[gw + 1];
    float adh = ad[(size_t)gw * 4 + hh];
    float4 acc = make_float4(0.f, 0.f, 0.f, 0.f);
    float wsum = 0.f;
    for (int i = beg + hl; i < end; i += 2) {
        int s = csrsrc[i];
        float asv = as[(size_t)s * 4 + hh];
        float t = asv + adh; t = t > 0.f ? t : NEG_SLOPE * t;
        float w = __expf(t);
        wsum += w;
        uint2 raw = *reinterpret_cast<const uint2*>(h + (size_t)s * F2 + c0);
        float2 f0 = __half22float2(*reinterpret_cast<__half2*>(&raw.x));
        float2 f1 = __half22float2(*reinterpret_cast<__half2*>(&raw.y));
        acc.x += w * f0.x; acc.y += w * f0.y;
        acc.z += w * f1.x; acc.w += w * f1.y;
    }
    // combine the two edge-halves (same channels, disjoint edge sets)
    acc.x += __shfl_xor_sync(0xffffffffu, acc.x, 16);
    acc.y += __shfl_xor_sync(0xffffffffu, acc.y, 16);
    acc.z += __shfl_xor_sync(0xffffffffu, acc.z, 16);
    acc.w += __shfl_xor_sync(0xffffffffu, acc.w, 16);
    wsum  += __shfl_xor_sync(0xffffffffu, wsum, 16);
    if (lane < 16) {
        float inv = 1.f / wsum;
        float4 b = *reinterpret_cast<const float4*>(bias + c0);
        float4 o;
        o.x = fmaxf(acc.x * inv + b.x, 0.f);
        o.y = fmaxf(acc.y * inv + b.y, 0.f);
        o.z = fmaxf(acc.z * inv + b.z, 0.f);
        o.w = fmaxf(acc.w * inv + b.w, 0.f);
        *reinterpret_cast<float4*>(out + (size_t)gw * F2 + c0) = o;
    }
}

// ---------------- pooling (batch sorted; 8 nodes/thread run-length) --------
#define POOL_CH 8
__global__ void pool_kernel(const float* __restrict__ g, const int* __restrict__ batch,
                            float* __restrict__ pool, int N) {
    int c = blockIdx.y;
    int t = blockIdx.x * blockDim.x + threadIdx.x;
    int n0 = t * POOL_CH;
    if (n0 >= N) return;
    int n1 = min(N, n0 + POOL_CH);
    int cur = batch[n0];
    float acc = 0.f;
    for (int n = n0; n < n1; n++) {
        int bb = batch[n];
        if (bb != cur) { atomicAdd(&pool[cur * F2 + c], acc); cur = bb; acc = 0.f; }
        acc += g[(size_t)n * F2 + c];
    }
    atomicAdd(&pool[cur * F2 + c], acc);
}

__global__ void count_kernel(const int* __restrict__ batch, float* __restrict__ cnt, int N) {
    int t = blockIdx.x * blockDim.x + threadIdx.x;
    int n0 = t * POOL_CH;
    if (n0 >= N) return;
    int n1 = min(N, n0 + POOL_CH);
    int cur = batch[n0];
    float acc = 0.f;
    for (int n = n0; n < n1; n++) {
        int bb = batch[n];
        if (bb != cur) { atomicAdd(&cnt[cur], acc); cur = bb; acc = 0.f; }
        acc += 1.f;
    }
    atomicAdd(&cnt[cur], acc);
}

// ---------------- final FC --------------------------------------------------
__global__ void fc_kernel(const float* __restrict__ pool, const float* __restrict__ cnt,
                          const float* __restrict__ w, const float* __restrict__ b,
                          float* __restrict__ out) {
    int g = blockIdx.x;
    int j = threadIdx.x;
    float inv = 1.f / fmaxf(cnt[g], 1.f);
    float acc = b[j];
#pragma unroll
    for (int c = 0; c < F2; c++)
        acc += pool[g * F2 + c] * inv * w[c * NOUT + j];
    out[g * NOUT + j] = acc;
}

// ---------------- launch ----------------------------------------------------
extern "C" void kernel_launch(void* const* d_in, const int* in_sizes, int n_in,
                              void* d_out, int out_size) {
    const float* x      = (const float*)d_in[0];
    const int*   ei     = (const int*)  d_in[1];
    const int*   batch  = (const int*)  d_in[2];
    const float* W1     = (const float*)d_in[3];
    const float* a_src1 = (const float*)d_in[4];
    const float* a_dst1 = (const float*)d_in[5];
    const float* b1     = (const float*)d_in[6];
    const float* W2     = (const float*)d_in[7];
    const float* a_src2 = (const float*)d_in[8];
    const float* a_dst2 = (const float*)d_in[9];
    const float* b2     = (const float*)d_in[10];
    const float* fcw    = (const float*)d_in[11];
    const float* fcb    = (const float*)d_in[12];

    int N = in_sizes[0] / F0;     // 50000
    int E = in_sizes[1] / 2;      // 800000
    int ET = E + N;

    __half *p_x16, *p_w1h, *p_w2h, *p_h1, *p_g1h, *p_h2;
    float *p_g2, *p_as, *p_ad, *p_pool, *p_cnt;
    int *p_deg, *p_rowptr, *p_rowpos, *p_csrsrc;
    cudaGetSymbolAddress((void**)&p_x16, d_x16);
    cudaGetSymbolAddress((void**)&p_w1h, d_w1h);
    cudaGetSymbolAddress((void**)&p_w2h, d_w2h);
    cudaGetSymbolAddress((void**)&p_h1, d_h1);
    cudaGetSymbolAddress((void**)&p_g1h, d_g1h);
    cudaGetSymbolAddress((void**)&p_h2, d_h2);
    cudaGetSymbolAddress((void**)&p_g2, d_g2);
    cudaGetSymbolAddress((void**)&p_as, d_as);
    cudaGetSymbolAddress((void**)&p_ad, d_ad);
    cudaGetSymbolAddress((void**)&p_deg, d_deg);
    cudaGetSymbolAddress((void**)&p_rowptr, d_rowptr);
    cudaGetSymbolAddress((void**)&p_rowpos, d_rowpos);
    cudaGetSymbolAddress((void**)&p_csrsrc, d_csrsrc);
    cudaGetSymbolAddress((void**)&p_pool, d_pool);
    cudaGetSymbolAddress((void**)&p_cnt, d_cnt);

    float* out = (float*)d_out;

    static cudaStream_t s2 = nullptr;
    static cudaEvent_t ev_fork = nullptr, ev_join = nullptr;
    if (s2 == nullptr) {
        cudaStreamCreateWithFlags(&s2, cudaStreamNonBlocking);
        cudaEventCreateWithFlags(&ev_fork, cudaEventDisableTiming);
        cudaEventCreateWithFlags(&ev_join, cudaEventDisableTiming);
    }

    // ---- fork: CSR build + pooling init on s2 (depends only on ei/batch) ----
    cudaEventRecord(ev_fork, 0);
    cudaStreamWaitEvent(s2, ev_fork, 0);
    cudaMemsetAsync(p_deg, 0, (size_t)N * sizeof(int), s2);
    hist_kernel<<<(ET + 255) / 256, 256, 0, s2>>>(ei, p_deg, E, N);
    scan_kernel<<<1, 1024, 0, s2>>>(p_deg, p_rowptr, p_rowpos, N);
    scatter_kernel<<<(ET + 255) / 256, 256, 0, s2>>>(ei, p_rowpos, p_csrsrc, E, N);
    cudaMemsetAsync(p_pool, 0, (size_t)NG * F2 * sizeof(float), s2);
    cudaMemsetAsync(p_cnt, 0, (size_t)NG * sizeof(float), s2);
    count_kernel<<<(((N + POOL_CH - 1) / POOL_CH) + 127) / 128, 128, 0, s2>>>(batch, p_cnt, N);
    cudaEventRecord(ev_join, s2);

    // ---- main stream: fp16 conversion + GEMM1 + alpha1 (independent) ----
    f2h_kernel<<<((N * F0 / 4) + 255) / 256, 256>>>((const float4*)x, (uint2*)p_x16, N * F0 / 4);
    f2h_kernel<<<((F0 * F1 / 4) + 255) / 256, 256>>>((const float4*)W1, (uint2*)p_w1h, F0 * F1 / 4);
    f2h_kernel<<<((F1 * F2 / 4) + 255) / 256, 256>>>((const float4*)W2, (uint2*)p_w2h, F1 * F2 / 4);
    {
        dim3 grid((N + 127) / 128, F1 / 64);
        gemm_f16<<<grid, 256>>>(p_x16, p_w1h, p_h1, N, F1, F0);
    }
    alpha_kernel<C1><<<(N * NHEAD + 255) / 256, 256>>>(p_h1, a_src1, a_dst1, p_as, p_ad, N);

    // ---- join: aggregation needs the CSR ----
    cudaStreamWaitEvent(0, ev_join, 0);
    agg1_kernel<<<(N * 32 + 255) / 256, 256>>>(p_rowptr, p_csrsrc, p_as, p_ad,
                                               p_h1, b1, p_g1h, N);

    // ---------------- layer 2 ----------------
    {
        dim3 grid((N + 127) / 128, F2 / 64);
        gemm_f16<<<grid, 256>>>(p_g1h, p_w2h, p_h2, N, F2, F1);
    }
    alpha_kernel<C2><<<(N * NHEAD + 255) / 256, 256>>>(p_h2, a_src2, a_dst2, p_as, p_ad, N);
    agg2_kernel<<<(N * 32 + 255) / 256, 256>>>(p_rowptr, p_csrsrc, p_as, p_ad,
                                               p_h2, b2, p_g2, N);

    // ---------------- pooling + FC ----------------
    {
        int nthreads = (N + POOL_CH - 1) / POOL_CH;
        dim3 grid((nthreads + 127) / 128, F2);
        pool_kernel<<<grid, 128>>>(p_g2, batch, p_pool, N);
    }
    fc_kernel<<<NG, NOUT>>>(p_pool, p_cnt, fcw, fcb, out);
}

// round 16
// speedup vs baseline: 1.1408x; 1.0431x over previous
#include <cuda_runtime.h>
#include <cuda_fp16.h>
#include <cstdint>

// ---------------- problem constants (fixed by setup_inputs) ----------------
#define NN   50000
#define EE   800000
#define ET_MAX (EE+NN)
#define F0   128
#define NHEAD 4
#define C1   64
#define F1   (NHEAD*C1)   // 256
#define C2   16
#define F2   (NHEAD*C2)   // 64
#define NG   64
#define NOUT 32
#define NEG_SLOPE 0.2f

// ---------------- scratch (device globals; no allocation allowed) ----------
__device__ __half d_x16[NN*F0];
__device__ __half d_w1h[F0*F1];
__device__ __half d_w2h[F1*F2];
__device__ __half d_h1[NN*F1];
__device__ __half d_g1h[NN*F1];
__device__ __half d_h2[NN*F2];
__device__ float  d_as[NN*NHEAD];
__device__ float  d_ad[NN*NHEAD];
__device__ int    d_deg[NN];
__device__ int    d_rowptr[NN+1];
__device__ int    d_rowpos[NN];
__device__ int    d_csrsrc[ET_MAX];
__device__ float  d_pool[NG*F2];
__device__ float  d_cnt[NG];

// ---------------- helpers ---------------------------------------------------
__device__ __forceinline__ void cp_async16(void* smem, const void* gmem) {
    uint32_t s = (uint32_t)__cvta_generic_to_shared(smem);
    asm volatile("cp.async.ca.shared.global [%0], [%1], 16;" :: "r"(s), "l"(gmem));
}
__device__ __forceinline__ void cp_commit() { asm volatile("cp.async.commit_group;"); }
__device__ __forceinline__ void cp_wait0()  { asm volatile("cp.async.wait_group 0;"); }

__device__ __forceinline__ uint32_t smem_u32(const void* p) {
    return (uint32_t)__cvta_generic_to_shared(p);
}
__device__ __forceinline__ void ldsm_x4(uint32_t& r0, uint32_t& r1, uint32_t& r2, uint32_t& r3,
                                        uint32_t addr) {
    asm volatile("ldmatrix.sync.aligned.m8n8.x4.shared.b16 {%0,%1,%2,%3}, [%4];"
                 : "=r"(r0), "=r"(r1), "=r"(r2), "=r"(r3) : "r"(addr));
}
__device__ __forceinline__ void ldsm_x4_t(uint32_t& r0, uint32_t& r1, uint32_t& r2, uint32_t& r3,
                                          uint32_t addr) {
    asm volatile("ldmatrix.sync.aligned.m8n8.x4.trans.shared.b16 {%0,%1,%2,%3}, [%4];"
                 : "=r"(r0), "=r"(r1), "=r"(r2), "=r"(r3) : "r"(addr));
}
__device__ __forceinline__ void mma_f16(float* d, uint32_t a0, uint32_t a1, uint32_t a2,
                                        uint32_t a3, uint32_t b0, uint32_t b1) {
    asm volatile(
        "mma.sync.aligned.m16n8k16.row.col.f32.f16.f16.f32 "
        "{%0,%1,%2,%3}, {%4,%5,%6,%7}, {%8,%9}, {%0,%1,%2,%3};"
        : "+f"(d[0]), "+f"(d[1]), "+f"(d[2]), "+f"(d[3])
        : "r"(a0), "r"(a1), "r"(a2), "r"(a3), "r"(b0), "r"(b1));
}
__device__ __forceinline__ void red_add_v4(float* p, float4 v) {
    asm volatile("red.global.add.v4.f32 [%0], {%1,%2,%3,%4};"
                 :: "l"(p), "f"(v.x), "f"(v.y), "f"(v.z), "f"(v.w) : "memory");
}

// ---------------- fp32 -> fp16 convert (4 elems/thread) ---------------------
__global__ void f2h_kernel(const float4* __restrict__ in, uint2* __restrict__ out, int n4) {
    int i = blockIdx.x * blockDim.x + threadIdx.x;
    if (i >= n4) return;
    float4 v = in[i];
    __half2 a = __floats2half2_rn(v.x, v.y);
    __half2 b = __floats2half2_rn(v.z, v.w);
    uint2 o;
    o.x = *reinterpret_cast<uint32_t*>(&a);
    o.y = *reinterpret_cast<uint32_t*>(&b);
    out[i] = o;
}

// ---------------- fp16 HMMA GEMM + fused alpha epilogue --------------------
// CH = channels per head. Block covers 64 cols = 64/CH heads.
// Writes C (fp16) AND alpha_src/alpha_dst dot-products per (row, head).
template<int CH>
__global__ __launch_bounds__(256) void gemm_f16_alpha(
    const __half* __restrict__ A, const __half* __restrict__ B,
    __half* __restrict__ C, int M, int N, int K,
    const float* __restrict__ asr, const float* __restrict__ adt,
    float* __restrict__ as_out, float* __restrict__ ad_out)
{
    __shared__ __half As[2][128][40];
    __shared__ __half Bs[2][32][72];
    __shared__ float sAS[128][4];
    __shared__ float sAD[128][4];

    int tid  = threadIdx.x;
    int warp = tid >> 5, lane = tid & 31;
    int wm = (warp & 3) * 32;
    int wn = (warp >> 2) * 32;
    int m0 = blockIdx.x * 128;
    int n0 = blockIdx.y * 64;

    int r  = lane >> 2;
    int cg = lane & 3;
    int g  = lane >> 3;
    int lr = lane & 7;
    int rowoff = (g & 1) * 8 + lr;
    int coloff = (g >> 1) * 8;

    int arow = tid >> 2;
    int akc  = (tid & 3) * 8;
    int brow = tid >> 3;
    int bnc  = (tid & 7) * 8;

    // zero alpha scratch (epilogue-only; safe before the loop)
    {
        float* flat = &sAS[0][0];
        flat[tid] = 0.f; flat[tid + 256] = 0.f;
        float* flat2 = &sAD[0][0];
        flat2[tid] = 0.f; flat2[tid + 256] = 0.f;
    }

    float acc[2][4][4];
#pragma unroll
    for (int i = 0; i < 2; i++)
#pragma unroll
        for (int j = 0; j < 4; j++)
#pragma unroll
            for (int q = 0; q < 4; q++) acc[i][j][q] = 0.f;

    int nk = K >> 5;

    {
        int gm0 = m0 + arow;       if (gm0 > M - 1) gm0 = M - 1;
        int gm1 = m0 + arow + 64;  if (gm1 > M - 1) gm1 = M - 1;
        cp_async16(&As[0][arow     ][akc], &A[(size_t)gm0 * K + akc]);
        cp_async16(&As[0][arow + 64][akc], &A[(size_t)gm1 * K + akc]);
        cp_async16(&Bs[0][brow][bnc], &B[(size_t)brow * N + n0 + bnc]);
        cp_commit();
    }

    for (int t = 0; t < nk; t++) {
        cp_wait0();
        __syncthreads();
        int buf = t & 1;

        if (t + 1 < nk) {
            int k0 = (t + 1) << 5;
            int gm0 = m0 + arow;       if (gm0 > M - 1) gm0 = M - 1;
            int gm1 = m0 + arow + 64;  if (gm1 > M - 1) gm1 = M - 1;
            cp_async16(&As[buf ^ 1][arow     ][akc], &A[(size_t)gm0 * K + k0 + akc]);
            cp_async16(&As[buf ^ 1][arow + 64][akc], &A[(size_t)gm1 * K + k0 + akc]);
            cp_async16(&Bs[buf ^ 1][brow][bnc], &B[(size_t)(k0 + brow) * N + n0 + bnc]);
            cp_commit();
        }

#pragma unroll
        for (int ks = 0; ks < 32; ks += 16) {
            uint32_t a[2][4];
#pragma unroll
            for (int mt = 0; mt < 2; mt++)
                ldsm_x4(a[mt][0], a[mt][1], a[mt][2], a[mt][3],
                        smem_u32(&As[buf][wm + mt * 16 + rowoff][ks + coloff]));
            uint32_t b[4][2];
#pragma unroll
            for (int np = 0; np < 2; np++) {
                uint32_t r0, r1, r2, r3;
                ldsm_x4_t(r0, r1, r2, r3,
                          smem_u32(&Bs[buf][ks + rowoff][wn + np * 16 + coloff]));
                b[np * 2][0] = r0; b[np * 2][1] = r1;
                b[np * 2 + 1][0] = r2; b[np * 2 + 1][1] = r3;
            }
#pragma unroll
            for (int mt = 0; mt < 2; mt++)
#pragma unroll
                for (int nt = 0; nt < 4; nt++)
                    mma_f16(acc[mt][nt], a[mt][0], a[mt][1], a[mt][2], a[mt][3],
                            b[nt][0], b[nt][1]);
        }
        __syncthreads();
    }

    // ---- store C (fp16) ----
#pragma unroll
    for (int mt = 0; mt < 2; mt++) {
#pragma unroll
        for (int nt = 0; nt < 4; nt++) {
            int row = m0 + wm + mt * 16 + r;
            int col = n0 + wn + nt * 8 + 2 * cg;
            if (row < M) {
                __half2 o = __floats2half2_rn(acc[mt][nt][0], acc[mt][nt][1]);
                *reinterpret_cast<__half2*>(&C[(size_t)row * N + col]) = o;
            }
            if (row + 8 < M) {
                __half2 o = __floats2half2_rn(acc[mt][nt][2], acc[mt][nt][3]);
                *reinterpret_cast<__half2*>(&C[(size_t)(row + 8) * N + col]) = o;
            }
        }
    }

    // ---- fused alpha: per-row dot with asr/adt over this block's 64 cols ----
#pragma unroll
    for (int mt = 0; mt < 2; mt++) {
#pragma unroll
        for (int nt = 0; nt < 4; nt++) {
            int cbase = n0 + wn + nt * 8 + 2 * cg;
            float v0 = asr[cbase], v1 = asr[cbase + 1];
            float u0 = adt[cbase], u1 = adt[cbase + 1];
            float s0 = acc[mt][nt][0] * v0 + acc[mt][nt][1] * v1;   // row r
            float s1 = acc[mt][nt][2] * v0 + acc[mt][nt][3] * v1;   // row r+8
            float d0 = acc[mt][nt][0] * u0 + acc[mt][nt][1] * u1;
            float d1 = acc[mt][nt][2] * u0 + acc[mt][nt][3] * u1;
            // reduce across the 4 cg lanes (col groups)
            s0 += __shfl_xor_sync(0xffffffffu, s0, 1); s0 += __shfl_xor_sync(0xffffffffu, s0, 2);
            s1 += __shfl_xor_sync(0xffffffffu, s1, 1); s1 += __shfl_xor_sync(0xffffffffu, s1, 2);
            d0 += __shfl_xor_sync(0xffffffffu, d0, 1); d0 += __shfl_xor_sync(0xffffffffu, d0, 2);
            d1 += __shfl_xor_sync(0xffffffffu, d1, 1); d1 += __shfl_xor_sync(0xffffffffu, d1, 2);
            if (cg == 0) {
                int hb = (wn + nt * 8) / CH;   // head slot within block
                int rw = wm + mt * 16 + r;
                atomicAdd(&sAS[rw][hb], s0);
                atomicAdd(&sAS[rw + 8][hb], s1);
                atomicAdd(&sAD[rw][hb], d0);
                atomicAdd(&sAD[rw + 8][hb], d1);
            }
        }
    }
    __syncthreads();
    if (tid < 128) {
        int row = m0 + tid;
        if (row < M) {
            const int NH_BLK = 64 / CH;            // heads covered by this block
            int hbase = n0 / CH;
#pragma unroll
            for (int hb = 0; hb < NH_BLK; hb++) {
                as_out[(size_t)row * NHEAD + hbase + hb] = sAS[tid][hb];
                ad_out[(size_t)row * NHEAD + hbase + hb] = sAD[tid][hb];
            }
        }
    }
}

// ---------------- CSR build: histogram -> scan -> scatter -------------------
__global__ void hist_kernel(const int* __restrict__ ei, int* __restrict__ deg,
                            int E, int N) {
    int e = blockIdx.x * blockDim.x + threadIdx.x;
    if (e >= E + N) return;
    int d = (e < E) ? ei[E + e] : (e - E);
    atomicAdd(&deg[d], 1);
}

__global__ void scan_kernel(const int* __restrict__ deg, int* __restrict__ rowptr,
                            int* __restrict__ rowpos, int N) {
    __shared__ int sums[1024];
    int t = threadIdx.x;
    int CH = (N + 1023) / 1024;
    int b = t * CH, e = min(N, b + CH);
    int s = 0;
    for (int i = b; i < e; i++) s += deg[i];
    sums[t] = s;
    __syncthreads();
    for (int off = 1; off < 1024; off <<= 1) {
        int v = (t >= off) ? sums[t - off] : 0;
        __syncthreads();
        sums[t] += v;
        __syncthreads();
    }
    int run = (t == 0) ? 0 : sums[t - 1];
    for (int i = b; i < e; i++) {
        rowptr[i] = run;
        rowpos[i] = run;
        run += deg[i];
    }
    if (t == 1023) rowptr[N] = sums[1023];
}

__global__ void scatter_kernel(const int* __restrict__ ei, int* __restrict__ rowpos,
                               int* __restrict__ csrsrc, int E, int N) {
    int e = blockIdx.x * blockDim.x + threadIdx.x;
    if (e >= E + N) return;
    int s, d;
    if (e < E) { s = ei[e]; d = ei[E + e]; } else { s = d = e - E; }
    int pos = atomicAdd(&rowpos[d], 1);
    csrsrc[pos] = s;
}

// ---------------- pull aggregation layer 1 (warp per dst, all heads) -------
__global__ void agg1_kernel(const int* __restrict__ rowptr, const int* __restrict__ csrsrc,
                            const float* __restrict__ as, const float* __restrict__ ad,
                            const __half* __restrict__ h,
                            const float* __restrict__ bias, __half* __restrict__ out, int N) {
    int gw = (blockIdx.x * blockDim.x + threadIdx.x) >> 5;
    int lane = threadIdx.x & 31;
    if (gw >= N) return;
    int hh = lane >> 3;
    int beg = rowptr[gw], end = rowptr[gw + 1];
    float adh = ad[(size_t)gw * 4 + hh];
    float4 acc0 = make_float4(0.f, 0.f, 0.f, 0.f);
    float4 acc1 = make_float4(0.f, 0.f, 0.f, 0.f);
    float wsum = 0.f;
    int i = beg;
    for (; i + 1 < end; i += 2) {
        int s0 = csrsrc[i], s1 = csrsrc[i + 1];
        float as0 = as[(size_t)s0 * 4 + hh];
        float as1 = as[(size_t)s1 * 4 + hh];
        uint4 ra = *reinterpret_cast<const uint4*>(h + (size_t)s0 * F1 + lane * 8);
        uint4 rb = *reinterpret_cast<const uint4*>(h + (size_t)s1 * F1 + lane * 8);
        float t0 = as0 + adh; t0 = t0 > 0.f ? t0 : NEG_SLOPE * t0;
        float t1 = as1 + adh; t1 = t1 > 0.f ? t1 : NEG_SLOPE * t1;
        float w0 = __expf(t0), w1 = __expf(t1);
        wsum += w0 + w1;
        float2 f;
        f = __half22float2(*reinterpret_cast<__half2*>(&ra.x)); acc0.x += w0 * f.x; acc0.y += w0 * f.y;
        f = __half22float2(*reinterpret_cast<__half2*>(&ra.y)); acc0.z += w0 * f.x; acc0.w += w0 * f.y;
        f = __half22float2(*reinterpret_cast<__half2*>(&ra.z)); acc1.x += w0 * f.x; acc1.y += w0 * f.y;
        f = __half22float2(*reinterpret_cast<__half2*>(&ra.w)); acc1.z += w0 * f.x; acc1.w += w0 * f.y;
        f = __half22float2(*reinterpret_cast<__half2*>(&rb.x)); acc0.x += w1 * f.x; acc0.y += w1 * f.y;
        f = __half22float2(*reinterpret_cast<__half2*>(&rb.y)); acc0.z += w1 * f.x; acc0.w += w1 * f.y;
        f = __half22float2(*reinterpret_cast<__half2*>(&rb.z)); acc1.x += w1 * f.x; acc1.y += w1 * f.y;
        f = __half22float2(*reinterpret_cast<__half2*>(&rb.w)); acc1.z += w1 * f.x; acc1.w += w1 * f.y;
    }
    if (i < end) {
        int s0 = csrsrc[i];
        float as0 = as[(size_t)s0 * 4 + hh];
        float t0 = as0 + adh; t0 = t0 > 0.f ? t0 : NEG_SLOPE * t0;
        float w0 = __expf(t0);
        wsum += w0;
        uint4 ra = *reinterpret_cast<const uint4*>(h + (size_t)s0 * F1 + lane * 8);
        float2 f;
        f = __half22float2(*reinterpret_cast<__half2*>(&ra.x)); acc0.x += w0 * f.x; acc0.y += w0 * f.y;
        f = __half22float2(*reinterpret_cast<__half2*>(&ra.y)); acc0.z += w0 * f.x; acc0.w += w0 * f.y;
        f = __half22float2(*reinterpret_cast<__half2*>(&ra.z)); acc1.x += w0 * f.x; acc1.y += w0 * f.y;
        f = __half22float2(*reinterpret_cast<__half2*>(&ra.w)); acc1.z += w0 * f.x; acc1.w += w0 * f.y;
    }
    float inv = 1.f / wsum;
    int c = lane * 8;
    const float4* bp = reinterpret_cast<const float4*>(bias + c);
    float4 b0 = bp[0], b1 = bp[1];
    __half2 p0 = __floats2half2_rn(fmaxf(acc0.x * inv + b0.x, 0.f), fmaxf(acc0.y * inv + b0.y, 0.f));
    __half2 p1 = __floats2half2_rn(fmaxf(acc0.z * inv + b0.z, 0.f), fmaxf(acc0.w * inv + b0.w, 0.f));
    __half2 p2 = __floats2half2_rn(fmaxf(acc1.x * inv + b1.x, 0.f), fmaxf(acc1.y * inv + b1.y, 0.f));
    __half2 p3 = __floats2half2_rn(fmaxf(acc1.z * inv + b1.z, 0.f), fmaxf(acc1.w * inv + b1.w, 0.f));
    uint4 o;
    o.x = *reinterpret_cast<uint32_t*>(&p0);
    o.y = *reinterpret_cast<uint32_t*>(&p1);
    o.z = *reinterpret_cast<uint32_t*>(&p2);
    o.w = *reinterpret_cast<uint32_t*>(&p3);
    *reinterpret_cast<uint4*>(out + (size_t)gw * F1 + c) = o;
}

// ---------------- agg2 + fused mean-pool scatter ----------------------------
// Half-warp per edge; lane owns 4 channels. Post bias+relu values are
// red.global.add'ed straight into pool[batch[n]] (g2 buffer eliminated).
__global__ void agg2_kernel(const int* __restrict__ rowptr, const int* __restrict__ csrsrc,
                            const float* __restrict__ as, const float* __restrict__ ad,
                            const __half* __restrict__ h,
                            const float* __restrict__ bias, const int* __restrict__ batch,
                            float* __restrict__ pool, int N) {
    int gw = (blockIdx.x * blockDim.x + threadIdx.x) >> 5;
    int lane = threadIdx.x & 31;
    if (gw >= N) return;
    int hl = lane >> 4;
    int cl = lane & 15;
    int c0 = cl * 4;
    int hh = c0 >> 4;
    int beg = rowptr[gw], end = rowptr[gw + 1];
    float adh = ad[(size_t)gw * 4 + hh];
    float4 acc = make_float4(0.f, 0.f, 0.f, 0.f);
    float wsum = 0.f;
    for (int i = beg + hl; i < end; i += 2) {
        int s = csrsrc[i];
        float asv = as[(size_t)s * 4 + hh];
        float t = asv + adh; t = t > 0.f ? t : NEG_SLOPE * t;
        float w = __expf(t);
        wsum += w;
        uint2 raw = *reinterpret_cast<const uint2*>(h + (size_t)s * F2 + c0);
        float2 f0 = __half22float2(*reinterpret_cast<__half2*>(&raw.x));
        float2 f1 = __half22float2(*reinterpret_cast<__half2*>(&raw.y));
        acc.x += w * f0.x; acc.y += w * f0.y;
        acc.z += w * f1.x; acc.w += w * f1.y;
    }
    acc.x += __shfl_xor_sync(0xffffffffu, acc.x, 16);
    acc.y += __shfl_xor_sync(0xffffffffu, acc.y, 16);
    acc.z += __shfl_xor_sync(0xffffffffu, acc.z, 16);
    acc.w += __shfl_xor_sync(0xffffffffu, acc.w, 16);
    wsum  += __shfl_xor_sync(0xffffffffu, wsum, 16);
    if (lane < 16) {
        float inv = 1.f / wsum;
        float4 b = *reinterpret_cast<const float4*>(bias + c0);
        float4 o;
        o.x = fmaxf(acc.x * inv + b.x, 0.f);
        o.y = fmaxf(acc.y * inv + b.y, 0.f);
        o.z = fmaxf(acc.z * inv + b.z, 0.f);
        o.w = fmaxf(acc.w * inv + b.w, 0.f);
        int g = batch[gw];
        red_add_v4(&pool[(size_t)g * F2 + c0], o);
    }
}

// ---------------- count (batch sorted; run-length) --------------------------
#define POOL_CH 8
__global__ void count_kernel(const int* __restrict__ batch, float* __restrict__ cnt, int N) {
    int t = blockIdx.x * blockDim.x + threadIdx.x;
    int n0 = t * POOL_CH;
    if (n0 >= N) return;
    int n1 = min(N, n0 + POOL_CH);
    int cur = batch[n0];
    float acc = 0.f;
    for (int n = n0; n < n1; n++) {
        int bb = batch[n];
        if (bb != cur) { atomicAdd(&cnt[cur], acc); cur = bb; acc = 0.f; }
        acc += 1.f;
    }
    atomicAdd(&cnt[cur], acc);
}

// ---------------- final FC --------------------------------------------------
__global__ void fc_kernel(const float* __restrict__ pool, const float* __restrict__ cnt,
                          const float* __restrict__ w, const float* __restrict__ b,
                          float* __restrict__ out) {
    int g = blockIdx.x;
    int j = threadIdx.x;
    float inv = 1.f / fmaxf(cnt[g], 1.f);
    float acc = b[j];
#pragma unroll
    for (int c = 0; c < F2; c++)
        acc += pool[g * F2 + c] * inv * w[c * NOUT + j];
    out[g * NOUT + j] = acc;
}

// ---------------- launch ----------------------------------------------------
extern "C" void kernel_launch(void* const* d_in, const int* in_sizes, int n_in,
                              void* d_out, int out_size) {
    const float* x      = (const float*)d_in[0];
    const int*   ei     = (const int*)  d_in[1];
    const int*   batch  = (const int*)  d_in[2];
    const float* W1     = (const float*)d_in[3];
    const float* a_src1 = (const float*)d_in[4];
    const float* a_dst1 = (const float*)d_in[5];
    const float* b1     = (const float*)d_in[6];
    const float* W2     = (const float*)d_in[7];
    const float* a_src2 = (const float*)d_in[8];
    const float* a_dst2 = (const float*)d_in[9];
    const float* b2     = (const float*)d_in[10];
    const float* fcw    = (const float*)d_in[11];
    const float* fcb    = (const float*)d_in[12];

    int N = in_sizes[0] / F0;     // 50000
    int E = in_sizes[1] / 2;      // 800000
    int ET = E + N;

    __half *p_x16, *p_w1h, *p_w2h, *p_h1, *p_g1h, *p_h2;
    float *p_as, *p_ad, *p_pool, *p_cnt;
    int *p_deg, *p_rowptr, *p_rowpos, *p_csrsrc;
    cudaGetSymbolAddress((void**)&p_x16, d_x16);
    cudaGetSymbolAddress((void**)&p_w1h, d_w1h);
    cudaGetSymbolAddress((void**)&p_w2h, d_w2h);
    cudaGetSymbolAddress((void**)&p_h1, d_h1);
    cudaGetSymbolAddress((void**)&p_g1h, d_g1h);
    cudaGetSymbolAddress((void**)&p_h2, d_h2);
    cudaGetSymbolAddress((void**)&p_as, d_as);
    cudaGetSymbolAddress((void**)&p_ad, d_ad);
    cudaGetSymbolAddress((void**)&p_deg, d_deg);
    cudaGetSymbolAddress((void**)&p_rowptr, d_rowptr);
    cudaGetSymbolAddress((void**)&p_rowpos, d_rowpos);
    cudaGetSymbolAddress((void**)&p_csrsrc, d_csrsrc);
    cudaGetSymbolAddress((void**)&p_pool, d_pool);
    cudaGetSymbolAddress((void**)&p_cnt, d_cnt);

    float* out = (float*)d_out;

    static cudaStream_t s2 = nullptr;
    static cudaEvent_t ev_fork = nullptr, ev_join = nullptr;
    if (s2 == nullptr) {
        cudaStreamCreateWithFlags(&s2, cudaStreamNonBlocking);
        cudaEventCreateWithFlags(&ev_fork, cudaEventDisableTiming);
        cudaEventCreateWithFlags(&ev_join, cudaEventDisableTiming);
    }

    // ---- fork: CSR build + pool init + count on s2 (ei/batch only) ----
    cudaEventRecord(ev_fork, 0);
    cudaStreamWaitEvent(s2, ev_fork, 0);
    cudaMemsetAsync(p_deg, 0, (size_t)N * sizeof(int), s2);
    hist_kernel<<<(ET + 255) / 256, 256, 0, s2>>>(ei, p_deg, E, N);
    scan_kernel<<<1, 1024, 0, s2>>>(p_deg, p_rowptr, p_rowpos, N);
    scatter_kernel<<<(ET + 255) / 256, 256, 0, s2>>>(ei, p_rowpos, p_csrsrc, E, N);
    cudaMemsetAsync(p_pool, 0, (size_t)NG * F2 * sizeof(float), s2);
    cudaMemsetAsync(p_cnt, 0, (size_t)NG * sizeof(float), s2);
    count_kernel<<<(((N + POOL_CH - 1) / POOL_CH) + 127) / 128, 128, 0, s2>>>(batch, p_cnt, N);
    cudaEventRecord(ev_join, s2);

    // ---- main stream: fp16 conversion + GEMM1 (alpha fused) ----
    f2h_kernel<<<((N * F0 / 4) + 255) / 256, 256>>>((const float4*)x, (uint2*)p_x16, N * F0 / 4);
    f2h_kernel<<<((F0 * F1 / 4) + 255) / 256, 256>>>((const float4*)W1, (uint2*)p_w1h, F0 * F1 / 4);
    f2h_kernel<<<((F1 * F2 / 4) + 255) / 256, 256>>>((const float4*)W2, (uint2*)p_w2h, F1 * F2 / 4);
    {
        dim3 grid((N + 127) / 128, F1 / 64);
        gemm_f16_alpha<C1><<<grid, 256>>>(p_x16, p_w1h, p_h1, N, F1, F0,
                                          a_src1, a_dst1, p_as, p_ad);
    }

    // ---- join: aggregation needs the CSR ----
    cudaStreamWaitEvent(0, ev_join, 0);
    agg1_kernel<<<(N * 32 + 255) / 256, 256>>>(p_rowptr, p_csrsrc, p_as, p_ad,
                                               p_h1, b1, p_g1h, N);

    // ---------------- layer 2 (alpha fused) ----------------
    {
        dim3 grid((N + 127) / 128, F2 / 64);
        gemm_f16_alpha<C2><<<grid, 256>>>(p_g1h, p_w2h, p_h2, N, F2, F1,
                                          a_src2, a_dst2, p_as, p_ad);
    }
    agg2_kernel<<<(N * 32 + 255) / 256, 256>>>(p_rowptr, p_csrsrc, p_as, p_ad,
                                               p_h2, b2, batch, p_pool, N);

    // ---------------- FC ----------------
    fc_kernel<<<NG, NOUT>>>(p_pool, p_cnt, fcw, fcb, out);
}